// round 3
// baseline (speedup 1.0000x reference)
#include <cuda_runtime.h>
#include <math.h>

#define N_NODES   100000
#define N_EDGES   1600000
#define N_GRAPHS  64
#define IN_FEATS  64
#define HIDDEN    32
#define OUT_DIM   2
#define CHUNKS    512

// Scratch (device globals — no allocation allowed)
__device__ float g_x32 [N_NODES * HIDDEN];   // x1 then x2 (reused)
__device__ float g_agg1[N_NODES * HIDDEN];
__device__ float g_agg2[N_NODES * HIDDEN];
__device__ float g_x3  [N_NODES * OUT_DIM];
__device__ float g_agg3[N_NODES * OUT_DIM];
__device__ float g_gsum[N_GRAPHS * IN_FEATS];
__device__ float g_gcnt[N_GRAPHS];
__device__ float g_c2  [HIDDEN];             // b1 @ W2
__device__ float g_c3  [OUT_DIM];            // b2 @ W3

__global__ void k_fill0(float* __restrict__ p, int n) {
    int i = blockIdx.x * blockDim.x + threadIdx.x;
    if (i < n) p[i] = 0.0f;
}

// c2 = b1 @ W2  (32), c3 = b2 @ W3 (2)
__global__ void k_bias(const float* __restrict__ b1, const float* __restrict__ W2,
                       const float* __restrict__ b2, const float* __restrict__ W3,
                       float* __restrict__ c2, float* __restrict__ c3) {
    int j = threadIdx.x;
    if (j < HIDDEN) {
        float s = 0.f;
        for (int k = 0; k < HIDDEN; k++) s += b1[k] * W2[k * HIDDEN + j];
        c2[j] = s;
    }
    if (j < OUT_DIM) {
        float s = 0.f;
        for (int k = 0; k < HIDDEN; k++) s += b2[k] * W3[k * OUT_DIM + j];
        c3[j] = s;
    }
}

// x = nf @ W1   [N,64] @ [64,32] ; warp per node, lane = out column
__global__ void k_mm1(const float* __restrict__ nf, const float* __restrict__ W1,
                      float* __restrict__ x) {
    __shared__ float Ws[IN_FEATS * HIDDEN];
    for (int i = threadIdx.x; i < IN_FEATS * HIDDEN; i += blockDim.x) Ws[i] = W1[i];
    __syncthreads();
    int warp   = (blockIdx.x * blockDim.x + threadIdx.x) >> 5;
    int lane   = threadIdx.x & 31;
    int nwarps = (gridDim.x * blockDim.x) >> 5;
    for (int n = warp; n < N_NODES; n += nwarps) {
        const float* row = nf + (size_t)n * IN_FEATS;
        float r0 = row[lane], r1 = row[lane + 32];
        float acc = 0.f;
        #pragma unroll
        for (int k = 0; k < 32; k++)
            acc += __shfl_sync(0xffffffffu, r0, k) * Ws[k * HIDDEN + lane];
        #pragma unroll
        for (int k = 0; k < 32; k++)
            acc += __shfl_sync(0xffffffffu, r1, k) * Ws[(k + 32) * HIDDEN + lane];
        x[(size_t)n * HIDDEN + lane] = acc;
    }
}

// x_out = agg @ W (+ c)   [N,32] @ [32,32] ; warp per node
__global__ void k_mm2(const float* __restrict__ agg, const float* __restrict__ W2,
                      const float* __restrict__ c2, float* __restrict__ x) {
    __shared__ float Ws[HIDDEN * HIDDEN];
    for (int i = threadIdx.x; i < HIDDEN * HIDDEN; i += blockDim.x) Ws[i] = W2[i];
    __syncthreads();
    int warp   = (blockIdx.x * blockDim.x + threadIdx.x) >> 5;
    int lane   = threadIdx.x & 31;
    int nwarps = (gridDim.x * blockDim.x) >> 5;
    float bias = c2[lane];
    for (int n = warp; n < N_NODES; n += nwarps) {
        float r = agg[(size_t)n * HIDDEN + lane];
        float acc = bias;
        #pragma unroll
        for (int k = 0; k < 32; k++)
            acc += __shfl_sync(0xffffffffu, r, k) * Ws[k * HIDDEN + lane];
        x[(size_t)n * HIDDEN + lane] = acc;
    }
}

// x3 = agg2 @ W3 + c3   [N,32] @ [32,2] ; thread per node
__global__ void k_mm3(const float* __restrict__ agg2, const float* __restrict__ W3,
                      const float* __restrict__ c3, float* __restrict__ x3) {
    __shared__ float Ws[HIDDEN * OUT_DIM];
    if (threadIdx.x < HIDDEN * OUT_DIM) Ws[threadIdx.x] = W3[threadIdx.x];
    __syncthreads();
    int n = blockIdx.x * blockDim.x + threadIdx.x;
    if (n >= N_NODES) return;
    float a0 = c3[0], a1 = c3[1];
    const float4* row = (const float4*)(agg2 + (size_t)n * HIDDEN);
    #pragma unroll
    for (int q = 0; q < 8; q++) {
        float4 v = row[q];
        int k = q * 4;
        a0 += v.x * Ws[(k + 0) * 2 + 0]; a1 += v.x * Ws[(k + 0) * 2 + 1];
        a0 += v.y * Ws[(k + 1) * 2 + 0]; a1 += v.y * Ws[(k + 1) * 2 + 1];
        a0 += v.z * Ws[(k + 2) * 2 + 0]; a1 += v.z * Ws[(k + 2) * 2 + 1];
        a0 += v.w * Ws[(k + 3) * 2 + 0]; a1 += v.w * Ws[(k + 3) * 2 + 1];
    }
    x3[(size_t)n * 2 + 0] = a0;
    x3[(size_t)n * 2 + 1] = a1;
}

// Scatter-add 32 floats/edge: 8 threads per edge, float4 each
__global__ void k_scatter32(const float* __restrict__ x, float* __restrict__ agg,
                            const int* __restrict__ src, const int* __restrict__ dst) {
    long long t     = (long long)blockIdx.x * blockDim.x + threadIdx.x;
    long long total = (long long)N_EDGES * 8;
    if (t >= total) return;
    int e = (int)(t >> 3), p = (int)(t & 7);
    int s = __ldg(src + e), d = __ldg(dst + e);
    float4 v = *(const float4*)(x + (size_t)s * HIDDEN + p * 4);
    float* a = agg + (size_t)d * HIDDEN + p * 4;
    atomicAdd(a + 0, v.x);
    atomicAdd(a + 1, v.y);
    atomicAdd(a + 2, v.z);
    atomicAdd(a + 3, v.w);
}

// Scatter-add 2 floats/edge: thread per edge
__global__ void k_scatter2(const float* __restrict__ x3, float* __restrict__ agg3,
                           const int* __restrict__ src, const int* __restrict__ dst) {
    int e = blockIdx.x * blockDim.x + threadIdx.x;
    if (e >= N_EDGES) return;
    int s = __ldg(src + e), d = __ldg(dst + e);
    float2 v = *(const float2*)(x3 + (size_t)s * 2);
    atomicAdd(agg3 + (size_t)d * 2 + 0, v.x);
    atomicAdd(agg3 + (size_t)d * 2 + 1, v.y);
}

// out[64 + n*2 + j] = agg3[n][j] + b3[j]
__global__ void k_h3out(const float* __restrict__ agg3, const float* __restrict__ b3,
                        float* __restrict__ out) {
    int i = blockIdx.x * blockDim.x + threadIdx.x;
    if (i >= N_NODES * OUT_DIM) return;
    out[N_GRAPHS + i] = agg3[i] + b3[i & 1];
}

// Per-graph feature sums + counts.  graph_ids is sorted, so each thread owns
// (feature f, contiguous node chunk) and flushes one atomic per graph-run.
__global__ void k_gsum(const float* __restrict__ nf, const int* __restrict__ gid,
                       float* __restrict__ gsum, float* __restrict__ gcnt) {
    int t = blockIdx.x * blockDim.x + threadIdx.x;
    if (t >= CHUNKS * IN_FEATS) return;
    int f = t & (IN_FEATS - 1);
    int chunk = t >> 6;
    const int per = (N_NODES + CHUNKS - 1) / CHUNKS;
    int n0 = chunk * per;
    int n1 = n0 + per; if (n1 > N_NODES) n1 = N_NODES;
    if (n0 >= n1) return;
    float acc = 0.f;
    int curg = gid[n0];
    for (int n = n0; n < n1; n++) {
        int g = gid[n];
        if (g != curg) { atomicAdd(&gsum[curg * IN_FEATS + f], acc); acc = 0.f; curg = g; }
        acc += nf[(size_t)n * IN_FEATS + f];
    }
    atomicAdd(&gsum[curg * IN_FEATS + f], acc);
    if (f == 0) {
        float c = 0.f;
        int cg = gid[n0];
        for (int n = n0; n < n1; n++) {
            int g = gid[n];
            if (g != cg) { atomicAdd(&gcnt[cg], c); c = 0.f; cg = g; }
            c += 1.f;
        }
        atomicAdd(&gcnt[cg], c);
    }
}

// out[g] = sigmoid( mean(nf over graph g) @ Wl + bl )
__global__ void k_pred(const float* __restrict__ Wl, const float* __restrict__ bl,
                       const float* __restrict__ gsum, const float* __restrict__ gcnt,
                       float* __restrict__ out) {
    int g = threadIdx.x;
    if (g >= N_GRAPHS) return;
    float cnt = gcnt[g]; if (cnt < 1.f) cnt = 1.f;
    float s = bl[0];
    #pragma unroll 8
    for (int f = 0; f < IN_FEATS; f++)
        s += (gsum[g * IN_FEATS + f] / cnt) * Wl[f];
    out[g] = 1.f / (1.f + expf(-s));
}

extern "C" void kernel_launch(void* const* d_in, const int* in_sizes, int n_in,
                              void* d_out, int out_size) {
    const float* nf  = (const float*)d_in[0];
    // d_in[1] = edge_feats (unused by the reference model)
    const float* W1  = (const float*)d_in[2];
    const float* b1  = (const float*)d_in[3];
    const float* W2  = (const float*)d_in[4];
    const float* b2  = (const float*)d_in[5];
    const float* W3  = (const float*)d_in[6];
    const float* b3  = (const float*)d_in[7];
    const float* Wl  = (const float*)d_in[8];
    const float* bl  = (const float*)d_in[9];
    const int*   src = (const int*)d_in[10];
    const int*   dst = (const int*)d_in[11];
    const int*   gid = (const int*)d_in[12];
    float* out = (float*)d_out;

    float *p_x32, *p_agg1, *p_agg2, *p_x3, *p_agg3, *p_gsum, *p_gcnt, *p_c2, *p_c3;
    cudaGetSymbolAddress((void**)&p_x32,  g_x32);
    cudaGetSymbolAddress((void**)&p_agg1, g_agg1);
    cudaGetSymbolAddress((void**)&p_agg2, g_agg2);
    cudaGetSymbolAddress((void**)&p_x3,   g_x3);
    cudaGetSymbolAddress((void**)&p_agg3, g_agg3);
    cudaGetSymbolAddress((void**)&p_gsum, g_gsum);
    cudaGetSymbolAddress((void**)&p_gcnt, g_gcnt);
    cudaGetSymbolAddress((void**)&p_c2,   g_c2);
    cudaGetSymbolAddress((void**)&p_c3,   g_c3);

    const int T = 256;
    // zero accumulators
    k_fill0<<<(N_NODES * HIDDEN  + T - 1) / T, T>>>(p_agg1, N_NODES * HIDDEN);
    k_fill0<<<(N_NODES * HIDDEN  + T - 1) / T, T>>>(p_agg2, N_NODES * HIDDEN);
    k_fill0<<<(N_NODES * OUT_DIM + T - 1) / T, T>>>(p_agg3, N_NODES * OUT_DIM);
    k_fill0<<<(N_GRAPHS * IN_FEATS + T - 1) / T, T>>>(p_gsum, N_GRAPHS * IN_FEATS);
    k_fill0<<<1, N_GRAPHS>>>(p_gcnt, N_GRAPHS);

    // folded bias constants
    k_bias<<<1, 32>>>(b1, W2, b2, W3, p_c2, p_c3);

    // layer 1: x1 = nf @ W1 ; agg1 = A x1
    k_mm1<<<(N_NODES * 32 + T - 1) / T, T>>>(nf, W1, p_x32);
    {
        long long tot = (long long)N_EDGES * 8;
        k_scatter32<<<(int)((tot + T - 1) / T), T>>>(p_x32, p_agg1, src, dst);
    }
    // layer 2: x2 = agg1 @ W2 + b1@W2 ; agg2 = A x2
    k_mm2<<<(N_NODES * 32 + T - 1) / T, T>>>(p_agg1, W2, p_c2, p_x32);
    {
        long long tot = (long long)N_EDGES * 8;
        k_scatter32<<<(int)((tot + T - 1) / T), T>>>(p_x32, p_agg2, src, dst);
    }
    // layer 3: x3 = agg2 @ W3 + b2@W3 ; agg3 = A x3 ; h3 = agg3 + b3
    k_mm3<<<(N_NODES + T - 1) / T, T>>>(p_agg2, W3, p_c3, p_x3);
    k_scatter2<<<(N_EDGES + T - 1) / T, T>>>(p_x3, p_agg3, src, dst);
    k_h3out<<<(N_NODES * OUT_DIM + T - 1) / T, T>>>(p_agg3, b3, out);

    // graph head: mean-pool of original features -> sigmoid(linear)
    k_gsum<<<(CHUNKS * IN_FEATS + T - 1) / T, T>>>(nf, gid, p_gsum, p_gcnt);
    k_pred<<<1, N_GRAPHS>>>(Wl, bl, p_gsum, p_gcnt, out);
}

// round 6
// speedup vs baseline: 1.5357x; 1.5357x over previous
#include <cuda_runtime.h>
#include <math.h>

#define N_NODES   100000
#define N_EDGES   1600000
#define N_GRAPHS  64
#define IN_FEATS  64
#define HIDDEN    32
#define OUT_DIM   2
#define CHUNKS    512

// Scratch (device globals — no allocation allowed). 16B-aligned for RED.128 / LDG.128.
__device__ __align__(16) float g_x32 [N_NODES * HIDDEN];   // x1 then x2 (reused)
__device__ __align__(16) float g_agg1[N_NODES * HIDDEN];
__device__ __align__(16) float g_agg2[N_NODES * HIDDEN];
__device__ __align__(16) float g_x3  [N_NODES * OUT_DIM];
__device__ __align__(16) float g_gsum[N_GRAPHS * IN_FEATS];
__device__ float g_gcnt[N_GRAPHS];
__device__ float g_c2  [HIDDEN];             // b1 @ W2
__device__ float g_c3  [OUT_DIM];            // b2 @ W3

// Vectorized zero fill (n must be multiple of 4 — all our buffers are)
__global__ void k_fill0v(float4* __restrict__ p, int n4) {
    int i = blockIdx.x * blockDim.x + threadIdx.x;
    if (i < n4) p[i] = make_float4(0.f, 0.f, 0.f, 0.f);
}

// Seed h3 output region with b3 (scatter2 REDs on top of it)
__global__ void k_init3(float* __restrict__ out, const float* __restrict__ b3) {
    int i = blockIdx.x * blockDim.x + threadIdx.x;
    if (i >= N_NODES * OUT_DIM) return;
    out[N_GRAPHS + i] = b3[i & 1];
}

// c2 = b1 @ W2  (32), c3 = b2 @ W3 (2)
__global__ void k_bias(const float* __restrict__ b1, const float* __restrict__ W2,
                       const float* __restrict__ b2, const float* __restrict__ W3,
                       float* __restrict__ c2, float* __restrict__ c3) {
    int j = threadIdx.x;
    if (j < HIDDEN) {
        float s = 0.f;
        for (int k = 0; k < HIDDEN; k++) s += b1[k] * W2[k * HIDDEN + j];
        c2[j] = s;
    }
    if (j < OUT_DIM) {
        float s = 0.f;
        for (int k = 0; k < HIDDEN; k++) s += b2[k] * W3[k * OUT_DIM + j];
        c3[j] = s;
    }
}

// x = nf @ W1   [N,64] @ [64,32] ; warp per node, lane = out column
__global__ void k_mm1(const float* __restrict__ nf, const float* __restrict__ W1,
                      float* __restrict__ x) {
    __shared__ float Ws[IN_FEATS * HIDDEN];
    for (int i = threadIdx.x; i < IN_FEATS * HIDDEN; i += blockDim.x) Ws[i] = W1[i];
    __syncthreads();
    int warp   = (blockIdx.x * blockDim.x + threadIdx.x) >> 5;
    int lane   = threadIdx.x & 31;
    int nwarps = (gridDim.x * blockDim.x) >> 5;
    for (int n = warp; n < N_NODES; n += nwarps) {
        const float* row = nf + (size_t)n * IN_FEATS;
        float r0 = row[lane], r1 = row[lane + 32];
        float acc = 0.f;
        #pragma unroll
        for (int k = 0; k < 32; k++)
            acc += __shfl_sync(0xffffffffu, r0, k) * Ws[k * HIDDEN + lane];
        #pragma unroll
        for (int k = 0; k < 32; k++)
            acc += __shfl_sync(0xffffffffu, r1, k) * Ws[(k + 32) * HIDDEN + lane];
        x[(size_t)n * HIDDEN + lane] = acc;
    }
}

// x_out = agg @ W (+ c)   [N,32] @ [32,32] ; warp per node
__global__ void k_mm2(const float* __restrict__ agg, const float* __restrict__ W2,
                      const float* __restrict__ c2, float* __restrict__ x) {
    __shared__ float Ws[HIDDEN * HIDDEN];
    for (int i = threadIdx.x; i < HIDDEN * HIDDEN; i += blockDim.x) Ws[i] = W2[i];
    __syncthreads();
    int warp   = (blockIdx.x * blockDim.x + threadIdx.x) >> 5;
    int lane   = threadIdx.x & 31;
    int nwarps = (gridDim.x * blockDim.x) >> 5;
    float bias = c2[lane];
    for (int n = warp; n < N_NODES; n += nwarps) {
        float r = agg[(size_t)n * HIDDEN + lane];
        float acc = bias;
        #pragma unroll
        for (int k = 0; k < 32; k++)
            acc += __shfl_sync(0xffffffffu, r, k) * Ws[k * HIDDEN + lane];
        x[(size_t)n * HIDDEN + lane] = acc;
    }
}

// x3 = agg2 @ W3 + c3   [N,32] @ [32,2] ; thread per node
__global__ void k_mm3(const float* __restrict__ agg2, const float* __restrict__ W3,
                      const float* __restrict__ c3, float* __restrict__ x3) {
    __shared__ float Ws[HIDDEN * OUT_DIM];
    if (threadIdx.x < HIDDEN * OUT_DIM) Ws[threadIdx.x] = W3[threadIdx.x];
    __syncthreads();
    int n = blockIdx.x * blockDim.x + threadIdx.x;
    if (n >= N_NODES) return;
    float a0 = c3[0], a1 = c3[1];
    const float4* row = (const float4*)(agg2 + (size_t)n * HIDDEN);
    #pragma unroll
    for (int q = 0; q < 8; q++) {
        float4 v = row[q];
        int k = q * 4;
        a0 += v.x * Ws[(k + 0) * 2 + 0]; a1 += v.x * Ws[(k + 0) * 2 + 1];
        a0 += v.y * Ws[(k + 1) * 2 + 0]; a1 += v.y * Ws[(k + 1) * 2 + 1];
        a0 += v.z * Ws[(k + 2) * 2 + 0]; a1 += v.z * Ws[(k + 2) * 2 + 1];
        a0 += v.w * Ws[(k + 3) * 2 + 0]; a1 += v.w * Ws[(k + 3) * 2 + 1];
    }
    x3[(size_t)n * 2 + 0] = a0;
    x3[(size_t)n * 2 + 1] = a1;
}

// Scatter-add 32 floats/edge: 8 threads per edge, one RED.128 (v4) per thread
__global__ void k_scatter32(const float* __restrict__ x, float* __restrict__ agg,
                            const int* __restrict__ src, const int* __restrict__ dst) {
    long long t     = (long long)blockIdx.x * blockDim.x + threadIdx.x;
    long long total = (long long)N_EDGES * 8;
    if (t >= total) return;
    int e = (int)(t >> 3), p = (int)(t & 7);
    int s = __ldg(src + e), d = __ldg(dst + e);
    float4 v = *(const float4*)(x + (size_t)s * HIDDEN + p * 4);
    float* a = agg + (size_t)d * HIDDEN + p * 4;
    asm volatile("red.global.add.v4.f32 [%0], {%1, %2, %3, %4};"
                 :: "l"(a), "f"(v.x), "f"(v.y), "f"(v.z), "f"(v.w) : "memory");
}

// Scatter-add 2 floats/edge directly into out+N_GRAPHS (pre-seeded with b3)
__global__ void k_scatter2(const float* __restrict__ x3, float* __restrict__ h3,
                           const int* __restrict__ src, const int* __restrict__ dst) {
    int e = blockIdx.x * blockDim.x + threadIdx.x;
    if (e >= N_EDGES) return;
    int s = __ldg(src + e), d = __ldg(dst + e);
    float2 v = *(const float2*)(x3 + (size_t)s * 2);
    float* a = h3 + (size_t)d * 2;
    asm volatile("red.global.add.v2.f32 [%0], {%1, %2};"
                 :: "l"(a), "f"(v.x), "f"(v.y) : "memory");
}

// Per-graph feature sums + counts (graph_ids sorted: one atomic per graph-run)
__global__ void k_gsum(const float* __restrict__ nf, const int* __restrict__ gid,
                       float* __restrict__ gsum, float* __restrict__ gcnt) {
    int t = blockIdx.x * blockDim.x + threadIdx.x;
    if (t >= CHUNKS * IN_FEATS) return;
    int f = t & (IN_FEATS - 1);
    int chunk = t >> 6;
    const int per = (N_NODES + CHUNKS - 1) / CHUNKS;
    int n0 = chunk * per;
    int n1 = n0 + per; if (n1 > N_NODES) n1 = N_NODES;
    if (n0 >= n1) return;
    float acc = 0.f;
    int curg = gid[n0];
    for (int n = n0; n < n1; n++) {
        int g = gid[n];
        if (g != curg) { atomicAdd(&gsum[curg * IN_FEATS + f], acc); acc = 0.f; curg = g; }
        acc += nf[(size_t)n * IN_FEATS + f];
    }
    atomicAdd(&gsum[curg * IN_FEATS + f], acc);
    if (f == 0) {
        float c = 0.f;
        int cg = gid[n0];
        for (int n = n0; n < n1; n++) {
            int g = gid[n];
            if (g != cg) { atomicAdd(&gcnt[cg], c); c = 0.f; cg = g; }
            c += 1.f;
        }
        atomicAdd(&gcnt[cg], c);
    }
}

// out[g] = sigmoid( mean(nf over graph g) @ Wl + bl )
__global__ void k_pred(const float* __restrict__ Wl, const float* __restrict__ bl,
                       const float* __restrict__ gsum, const float* __restrict__ gcnt,
                       float* __restrict__ out) {
    int g = threadIdx.x;
    if (g >= N_GRAPHS) return;
    float cnt = gcnt[g]; if (cnt < 1.f) cnt = 1.f;
    float s = bl[0];
    #pragma unroll 8
    for (int f = 0; f < IN_FEATS; f++)
        s += (gsum[g * IN_FEATS + f] / cnt) * Wl[f];
    out[g] = 1.f / (1.f + expf(-s));
}

extern "C" void kernel_launch(void* const* d_in, const int* in_sizes, int n_in,
                              void* d_out, int out_size) {
    const float* nf  = (const float*)d_in[0];
    // d_in[1] = edge_feats (unused by the reference model)
    const float* W1  = (const float*)d_in[2];
    const float* b1  = (const float*)d_in[3];
    const float* W2  = (const float*)d_in[4];
    const float* b2  = (const float*)d_in[5];
    const float* W3  = (const float*)d_in[6];
    const float* b3  = (const float*)d_in[7];
    const float* Wl  = (const float*)d_in[8];
    const float* bl  = (const float*)d_in[9];
    const int*   src = (const int*)d_in[10];
    const int*   dst = (const int*)d_in[11];
    const int*   gid = (const int*)d_in[12];
    float* out = (float*)d_out;

    float *p_x32, *p_agg1, *p_agg2, *p_x3, *p_gsum, *p_gcnt, *p_c2, *p_c3;
    cudaGetSymbolAddress((void**)&p_x32,  g_x32);
    cudaGetSymbolAddress((void**)&p_agg1, g_agg1);
    cudaGetSymbolAddress((void**)&p_agg2, g_agg2);
    cudaGetSymbolAddress((void**)&p_x3,   g_x3);
    cudaGetSymbolAddress((void**)&p_gsum, g_gsum);
    cudaGetSymbolAddress((void**)&p_gcnt, g_gcnt);
    cudaGetSymbolAddress((void**)&p_c2,   g_c2);
    cudaGetSymbolAddress((void**)&p_c3,   g_c3);

    const int T = 256;
    // zero accumulators (vectorized)
    k_fill0v<<<(N_NODES * HIDDEN / 4 + T - 1) / T, T>>>((float4*)p_agg1, N_NODES * HIDDEN / 4);
    k_fill0v<<<(N_NODES * HIDDEN / 4 + T - 1) / T, T>>>((float4*)p_agg2, N_NODES * HIDDEN / 4);
    k_fill0v<<<(N_GRAPHS * IN_FEATS / 4 + T - 1) / T, T>>>((float4*)p_gsum, N_GRAPHS * IN_FEATS / 4);
    k_fill0v<<<1, N_GRAPHS / 4>>>((float4*)p_gcnt, N_GRAPHS / 4);
    k_init3<<<(N_NODES * OUT_DIM + T - 1) / T, T>>>(out, b3);

    // folded bias constants
    k_bias<<<1, 32>>>(b1, W2, b2, W3, p_c2, p_c3);

    // layer 1: x1 = nf @ W1 ; agg1 = A x1
    k_mm1<<<(N_NODES * 32 + T - 1) / T, T>>>(nf, W1, p_x32);
    {
        long long tot = (long long)N_EDGES * 8;
        k_scatter32<<<(int)((tot + T - 1) / T), T>>>(p_x32, p_agg1, src, dst);
    }
    // layer 2: x2 = agg1 @ W2 + b1@W2 ; agg2 = A x2
    k_mm2<<<(N_NODES * 32 + T - 1) / T, T>>>(p_agg1, W2, p_c2, p_x32);
    {
        long long tot = (long long)N_EDGES * 8;
        k_scatter32<<<(int)((tot + T - 1) / T), T>>>(p_x32, p_agg2, src, dst);
    }
    // layer 3: x3 = agg2 @ W3 + b2@W3 ; h3 = A x3 + b3 (scattered straight into out)
    k_mm3<<<(N_NODES + T - 1) / T, T>>>(p_agg2, W3, p_c3, p_x3);
    k_scatter2<<<(N_EDGES + T - 1) / T, T>>>(p_x3, out + N_GRAPHS, src, dst);

    // graph head: mean-pool of original features -> sigmoid(linear)
    k_gsum<<<(CHUNKS * IN_FEATS + T - 1) / T, T>>>(nf, gid, p_gsum, p_gcnt);
    k_pred<<<1, N_GRAPHS>>>(Wl, bl, p_gsum, p_gcnt, out);
}